// round 15
// baseline (speedup 1.0000x reference)
#include <cuda_runtime.h>
#include <cuda_bf16.h>

// SubglacialDrainageSystem: L x = f on a 64x64 grid.
// Block cyclic reduction over the 64-block tridiagonal structure (BD=64).
// R15: k1inv uses RANK-8 windows (8 iterations instead of 16) -- per-iteration
// cost is stall-dominated, so halving the iteration count cuts the critical
// path. The 8x8 pivot-block inverse is a shuffle-based sweep on warp 0
// (2 elements/lane), pipelined one window ahead. kZ/k2/backsub as in R13.

#define NBLK 64
#define BD   64
#define BSZ  (BD * BD)

static __device__ float gA [NBLK * BSZ];
static __device__ float gAi[NBLK * BSZ];
static __device__ float gCb[2][NBLK * BSZ];
static __device__ float gBb[2][NBLK * BSZ];
static __device__ float gy [NBLK * BD];
static __device__ float gZC[NBLK * BSZ];
static __device__ float gZB[NBLK * BSZ];
static __device__ float gZy[NBLK * BD];

// ---------------------------------------------------------------------------
// Assembly
// ---------------------------------------------------------------------------
__global__ void assemble_kernel(const float* __restrict__ h,
                                const float* __restrict__ phi,
                                const float* __restrict__ base,
                                const float* __restrict__ over,
                                const float* __restrict__ melt,
                                const float* __restrict__ len,
                                const int*   __restrict__ adj,
                                const int*   __restrict__ io)
{
    int i = blockIdx.x * blockDim.x + threadIdx.x;
    if (i >= NBLK * BD) return;
    int r = i >> 6, a = i & 63;

    float4 z = make_float4(0.f, 0.f, 0.f, 0.f);
    float4* rowA = (float4*)(gA     + r * BSZ + a * BD);
    float4* rowC = (float4*)(gCb[0] + r * BSZ + a * BD);
    float4* rowB = (float4*)(gBb[0] + r * BSZ + a * BD);
#pragma unroll
    for (int b = 0; b < 16; b++) { rowA[b] = z; rowC[b] = z; rowB[b] = z; }

    const bool infl = (io[i] == 1);
    const double hi = (double)h[i];
    const double pi = (double)phi[i];
    double diag = 0.0, cf0 = 0.0, cf1 = 0.0, cf2 = 0.0, cf3 = 0.0;

#pragma unroll
    for (int k = 0; k < 4; k++) {           // 0 north, 1 south, 2 west, 3 east
        int   j = adj[i * 4 + k];
        float L = len[i * 4 + k];
        double cc = 0.0;
        if (j >= 0 && L > 0.0f && !infl) {
            double hf   = 0.5 * (hi + (double)h[j]);
            double dphi = fabs(pi - (double)phi[j]);
            double g    = fmax(dphi, 1e-12) / (double)L;
            cc = -0.01 * pow(hf, 1.25) * (double)L * rsqrt(g);
            diag -= cc;
        }
        if (k == 0) cf0 = cc; else if (k == 1) cf1 = cc;
        else if (k == 2) cf2 = cc; else cf3 = cc;
    }

    gA[r * BSZ + a * BD + a] = infl ? 1.0f : (float)diag;
    if (a > 0)  gA[r * BSZ + a * BD + (a - 1)] = (float)cf2;
    if (a < 63) gA[r * BSZ + a * BD + (a + 1)] = (float)cf3;
    gCb[0][r * BSZ + a * BD + a] = (float)cf0;
    gBb[0][r * BSZ + a * BD + a] = (float)cf1;
    gy[i] = infl ? (float)((double)base[i] - (double)over[i]) : melt[i];
}

// ---------------------------------------------------------------------------
// Warp-0 shuffle sweep inverse of an 8x8 matrix, 2 elements per lane:
// lane owns (a, c) in av0 and (a, c+4) in av1, a = lane>>2, c = lane&3.
// Sweep all 8 pivots -> av holds P^{-1} elements.
// ---------------------------------------------------------------------------
__device__ __forceinline__ void inv8_sweep(float& av0, float& av1, int a, int c)
{
    const unsigned FM = 0xFFFFFFFFu;
#pragma unroll
    for (int p = 0; p < 8; p++) {
        const bool plo = (p < 4);
        float App  = plo ? __shfl_sync(FM, av0, 4 * p + p)
                         : __shfl_sync(FM, av1, 4 * p + (p - 4));
        float Apc0 = __shfl_sync(FM, av0, 4 * p + c);
        float Apc1 = __shfl_sync(FM, av1, 4 * p + c);
        float Arp  = plo ? __shfl_sync(FM, av0, 4 * a + p)
                         : __shfl_sync(FM, av1, 4 * a + (p - 4));
        float rinv = __fdividef(1.0f, App);
        float n0, n1;
        if (a == p) {
            n0 = (c == p)     ? rinv : Apc0 * rinv;
            n1 = (c + 4 == p) ? rinv : Apc1 * rinv;
        } else {
            n0 = (c == p)     ? (-Arp * rinv) : (av0 - Arp * Apc0 * rinv);
            n1 = (c + 4 == p) ? (-Arp * rinv) : (av1 - Arp * Apc1 * rinv);
        }
        av0 = n0; av1 = n1;
    }
}

// ---------------------------------------------------------------------------
// K1: pipelined RANK-8 in-place GJ (sweep) inversion of [A | y] (width 65).
// 512 threads: rg = tid&31 owns rows {2rg, 2rg+1}; cg = tid>>5 owns cols
// [4cg, 4cg+4) (+y if cg==15). 8 iterations, one __syncthreads each;
// next-window 8x8 pivot inverse pipelined on warp 0.
// mode 0: epilogue ZC/ZB by diagonal column scaling (level 1)
// mode 1: epilogue writes Ainv to gAi (kZ forms ZC/ZB)
// mode 2: epilogue Zy only (top block)
// ---------------------------------------------------------------------------
__global__ void __launch_bounds__(512, 1)
k1inv(int s, int mode)
{
    const int j   = s - 1 + 2 * s * blockIdx.x;
    const int tid = threadIdx.x;
    const int rg  = tid & 31;
    const int cg  = tid >> 5;
    const int c0  = 4 * cg;
    const int r0  = 2 * rg;

    const float* Aj = gA + j * BSZ;

    float m[2][4], my[2];
#pragma unroll
    for (int r = 0; r < 2; r++) {
        float4 v = *(const float4*)&Aj[(r0 + r) * BD + c0];
        m[r][0] = v.x; m[r][1] = v.y; m[r][2] = v.z; m[r][3] = v.w;
        my[r] = (cg == 15) ? gy[j * BD + r0 + r] : 0.0f;
    }

    __shared__ float s_prow[2][8][68];     // current pivot rows (full width)
    __shared__ float s_pcol[2][64][8];     // current pivot cols, row-major
    __shared__ float s_pblk[2][8][8];      // NEXT window 8x8 block (raw)
    __shared__ float s_W[2][8][8];         // P^{-1}

    // ---- prologue: window 0 ---------------------------------------------
    if (rg < 4) {                          // rows 0..7 publish pivot rows
#pragma unroll
        for (int r = 0; r < 2; r++) {
            *(float4*)&s_prow[0][r0 + r][c0] =
                make_float4(m[r][0], m[r][1], m[r][2], m[r][3]);
            if (cg == 15) s_prow[0][r0 + r][64] = my[r];
        }
    }
    if (cg < 2) {                          // cols 0..7 -> pcol
#pragma unroll
        for (int r = 0; r < 2; r++)
            *(float4*)&s_pcol[0][r0 + r][4 * (cg & 1)] =
                make_float4(m[r][0], m[r][1], m[r][2], m[r][3]);
    }
    if ((cg == 2 || cg == 3) && (rg >> 2) == 1) {  // rows 8..15, cols 8..15
#pragma unroll
        for (int r = 0; r < 2; r++)
            *(float4*)&s_pblk[0][r0 + r - 8][4 * (cg & 1)] =
                make_float4(m[r][0], m[r][1], m[r][2], m[r][3]);
    }
    __syncthreads();
    if (tid < 32) {
        int a = tid >> 2, c = tid & 3;
        float av0 = s_pcol[0][a][c];
        float av1 = s_pcol[0][a][c + 4];
        inv8_sweep(av0, av1, a, c);
        s_W[0][a][c]     = av0;
        s_W[0][a][c + 4] = av1;
    }
    __syncthreads();

    // ---- 8 pipelined rank-8 sweep iterations -----------------------------
#pragma unroll 1
    for (int it = 0; it < 8; it++) {
        const int b  = it & 1;
        const int nb = b ^ 1;
        const int kn = 8 * it + 8;
        const bool ispiv = ((rg >> 2) == it);
        const int  wcg   = cg - 2 * it;          // 0/1 -> window column group

        // ---- u vectors (8 components per row) ---------------------------
        float u[2][8];
        {
            float4 va0 = *(const float4*)&s_pcol[b][r0][0];
            float4 va1 = *(const float4*)&s_pcol[b][r0][4];
            float4 vb0 = *(const float4*)&s_pcol[b][r0 + 1][0];
            float4 vb1 = *(const float4*)&s_pcol[b][r0 + 1][4];
            float va[8] = {va0.x, va0.y, va0.z, va0.w, va1.x, va1.y, va1.z, va1.w};
            float vb[8] = {vb0.x, vb0.y, vb0.z, vb0.w, vb1.x, vb1.y, vb1.z, vb1.w};
#pragma unroll
            for (int q = 0; q < 8; q++) { u[0][q] = 0.0f; u[1][q] = 0.0f; }
#pragma unroll
            for (int q = 0; q < 8; q++) {
                float4 w0 = *(const float4*)&s_W[b][q][0];
                float4 w1 = *(const float4*)&s_W[b][q][4];
                u[0][0] -= va[q] * w0.x; u[0][1] -= va[q] * w0.y;
                u[0][2] -= va[q] * w0.z; u[0][3] -= va[q] * w0.w;
                u[0][4] -= va[q] * w1.x; u[0][5] -= va[q] * w1.y;
                u[0][6] -= va[q] * w1.z; u[0][7] -= va[q] * w1.w;
                u[1][0] -= vb[q] * w0.x; u[1][1] -= vb[q] * w0.y;
                u[1][2] -= vb[q] * w0.z; u[1][3] -= vb[q] * w0.w;
                u[1][4] -= vb[q] * w1.x; u[1][5] -= vb[q] * w1.y;
                u[1][6] -= vb[q] * w1.z; u[1][7] -= vb[q] * w1.w;
            }
        }
        if (ispiv) {                        // pivot rows: u = W rows
            int lr0 = r0 - 8 * it;          // 0,2,4,6
#pragma unroll
            for (int r = 0; r < 2; r++) {
                float4 w0 = *(const float4*)&s_W[b][lr0 + r][0];
                float4 w1 = *(const float4*)&s_W[b][lr0 + r][4];
                u[r][0] = w0.x; u[r][1] = w0.y; u[r][2] = w0.z; u[r][3] = w0.w;
                u[r][4] = w1.x; u[r][5] = w1.y; u[r][6] = w1.z; u[r][7] = w1.w;
            }
        }

        // ---- column update ----------------------------------------------
        if (wcg == 0) {
#pragma unroll
            for (int r = 0; r < 2; r++)
#pragma unroll
                for (int t = 0; t < 4; t++) m[r][t] = u[r][t];
        } else if (wcg == 1) {
#pragma unroll
            for (int r = 0; r < 2; r++)
#pragma unroll
                for (int t = 0; t < 4; t++) m[r][t] = u[r][4 + t];
        } else {
#pragma unroll
            for (int r = 0; r < 2; r++)
                if (ispiv) { m[r][0] = 0.f; m[r][1] = 0.f; m[r][2] = 0.f; m[r][3] = 0.f; }
#pragma unroll
            for (int q = 0; q < 8; q++) {
                float4 pq = *(const float4*)&s_prow[b][q][c0];
#pragma unroll
                for (int r = 0; r < 2; r++) {
                    m[r][0] += u[r][q] * pq.x;
                    m[r][1] += u[r][q] * pq.y;
                    m[r][2] += u[r][q] * pq.z;
                    m[r][3] += u[r][q] * pq.w;
                }
            }
        }
        if (cg == 15) {                     // y column: unconditional
#pragma unroll
            for (int r = 0; r < 2; r++) if (ispiv) my[r] = 0.0f;
#pragma unroll
            for (int q = 0; q < 8; q++) {
                float py = s_prow[b][q][64];
                my[0] += u[0][q] * py;
                my[1] += u[1][q] * py;
            }
        }

        if (it < 7) {
            // ---- pipelined next-window 8x8 inverse (warp 0) -------------
            if (tid < 32) {
                int a = tid >> 2, c = tid & 3;
                float4 va0 = *(const float4*)&s_pcol[b][kn + a][0];
                float4 va1 = *(const float4*)&s_pcol[b][kn + a][4];
                float vv[8] = {va0.x, va0.y, va0.z, va0.w,
                               va1.x, va1.y, va1.z, va1.w};
                float t8[8];
#pragma unroll
                for (int q = 0; q < 8; q++) t8[q] = 0.0f;
#pragma unroll
                for (int q2 = 0; q2 < 8; q2++) {
                    float4 w0 = *(const float4*)&s_W[b][q2][0];
                    float4 w1 = *(const float4*)&s_W[b][q2][4];
                    t8[0] -= vv[q2] * w0.x; t8[1] -= vv[q2] * w0.y;
                    t8[2] -= vv[q2] * w0.z; t8[3] -= vv[q2] * w0.w;
                    t8[4] -= vv[q2] * w1.x; t8[5] -= vv[q2] * w1.y;
                    t8[6] -= vv[q2] * w1.z; t8[7] -= vv[q2] * w1.w;
                }
                float av0 = s_pblk[b][a][c];
                float av1 = s_pblk[b][a][c + 4];
#pragma unroll
                for (int q = 0; q < 8; q++) {
                    av0 += t8[q] * s_prow[b][q][kn + c];
                    av1 += t8[q] * s_prow[b][q][kn + c + 4];
                }
                inv8_sweep(av0, av1, a, c);
                s_W[nb][a][c]     = av0;
                s_W[nb][a][c + 4] = av1;
            }
            // ---- publishes for window kn --------------------------------
            if ((rg >> 2) == it + 1) {      // next pivot rows (raw)
#pragma unroll
                for (int r = 0; r < 2; r++) {
                    *(float4*)&s_prow[nb][r0 + r - kn][c0] =
                        make_float4(m[r][0], m[r][1], m[r][2], m[r][3]);
                    if (cg == 15) s_prow[nb][r0 + r - kn][64] = my[r];
                }
            }
            if (cg == 2 * it + 2 || cg == 2 * it + 3) {   // next pivot cols
#pragma unroll
                for (int r = 0; r < 2; r++)
                    *(float4*)&s_pcol[nb][r0 + r][4 * (cg & 1)] =
                        make_float4(m[r][0], m[r][1], m[r][2], m[r][3]);
            }
            if (it <= 5 && (cg == 2 * it + 4 || cg == 2 * it + 5)
                        && (rg >> 2) == it + 2) {         // pblk (2 ahead)
#pragma unroll
                for (int r = 0; r < 2; r++)
                    *(float4*)&s_pblk[nb][r0 + r - (kn + 8)][4 * (cg & 1)] =
                        make_float4(m[r][0], m[r][1], m[r][2], m[r][3]);
            }
        }
        __syncthreads();
    }

    // ---- epilogue --------------------------------------------------------
    if (cg == 15) {
        gZy[j * BD + r0]     = my[0];
        gZy[j * BD + r0 + 1] = my[1];
    }

    if (mode == 0) {
        const float* Cj = gCb[0] + j * BSZ;
        const float* Bj = gBb[0] + j * BSZ;
        float cd[4], bd[4];
#pragma unroll
        for (int t = 0; t < 4; t++) {
            cd[t] = Cj[(c0 + t) * 65];
            bd[t] = Bj[(c0 + t) * 65];
        }
#pragma unroll
        for (int r = 0; r < 2; r++) {
            *(float4*)&gZC[j * BSZ + (r0 + r) * BD + c0] =
                make_float4(m[r][0] * cd[0], m[r][1] * cd[1],
                            m[r][2] * cd[2], m[r][3] * cd[3]);
            *(float4*)&gZB[j * BSZ + (r0 + r) * BD + c0] =
                make_float4(m[r][0] * bd[0], m[r][1] * bd[1],
                            m[r][2] * bd[2], m[r][3] * bd[3]);
        }
    } else if (mode == 1) {
#pragma unroll
        for (int r = 0; r < 2; r++)
            *(float4*)&gAi[j * BSZ + (r0 + r) * BD + c0] =
                make_float4(m[r][0], m[r][1], m[r][2], m[r][3]);
    }
    // mode 2: Zy only
}

// ---------------------------------------------------------------------------
// kZ: ZC = Ainv * C (by=0) or ZB = Ainv * B (by=1). One 64^3 GEMM per CTA.
// ---------------------------------------------------------------------------
__global__ void __launch_bounds__(512, 1)
kZ(int s, int p)
{
    const int j     = s - 1 + 2 * s * blockIdx.x;
    const int which = blockIdx.y;
    const int tid   = threadIdx.x;
    const int rg    = tid & 31;
    const int cg    = tid >> 5;
    const int c0    = 4 * cg;
    const int r0    = 2 * rg;

    const float* src = (which ? gBb[p] : gCb[p]) + j * BSZ;
    float*       dst = (which ? gZB    : gZC)    + j * BSZ;

    __shared__ float sAi[64 * 65];
    for (int e = tid; e < BSZ; e += 512) {
        int r = e >> 6, c = e & 63;
        sAi[r * 65 + c] = gAi[j * BSZ + e];
    }
    __syncthreads();

    float4 acc0 = make_float4(0.f, 0.f, 0.f, 0.f);
    float4 acc1 = acc0;
#pragma unroll 4
    for (int k = 0; k < 64; k++) {
        float a0 = sAi[r0 * 65 + k];
        float a1 = sAi[(r0 + 1) * 65 + k];
        float4 v = __ldg((const float4*)&src[k * BD + c0]);
        acc0.x += a0 * v.x; acc0.y += a0 * v.y;
        acc0.z += a0 * v.z; acc0.w += a0 * v.w;
        acc1.x += a1 * v.x; acc1.y += a1 * v.y;
        acc1.z += a1 * v.z; acc1.w += a1 * v.w;
    }
    *(float4*)&dst[r0 * BD + c0]       = acc0;
    *(float4*)&dst[(r0 + 1) * BD + c0] = acc1;
}

// ---------------------------------------------------------------------------
// K2 level 1: C_i, B_i diagonal -> all Schur updates are row scalings.
// ---------------------------------------------------------------------------
__global__ void __launch_bounds__(256, 1)
k2_lvl1()
{
    const int i   = 1 + 2 * blockIdx.x;
    const int jm  = i - 1;
    const int jp  = (i + 1 > 63) ? 63 : (i + 1);
    const int tid = threadIdx.x;

    __shared__ float scd[64], sbd[64];
    if (tid < 64) {
        scd[tid] = gCb[0][i * BSZ + tid * 65];
        sbd[tid] = gBb[0][i * BSZ + tid * 65];
    }
    __syncthreads();

    for (int e = tid; e < 1024; e += 256) {
        int r  = e >> 4;
        int c4 = (e & 15) << 2;
        float cdr = scd[r], bdr = sbd[r];
        int off = r * BD + c4;

        float4 zbm = *(const float4*)&gZB[jm * BSZ + off];
        float4 zcp = *(const float4*)&gZC[jp * BSZ + off];
        float4 a   = *(const float4*)&gA [i * BSZ + off];
        a.x -= cdr * zbm.x + bdr * zcp.x;
        a.y -= cdr * zbm.y + bdr * zcp.y;
        a.z -= cdr * zbm.z + bdr * zcp.z;
        a.w -= cdr * zbm.w + bdr * zcp.w;
        *(float4*)&gA[i * BSZ + off] = a;

        float4 zcm = *(const float4*)&gZC[jm * BSZ + off];
        *(float4*)&gCb[1][i * BSZ + off] =
            make_float4(-cdr * zcm.x, -cdr * zcm.y, -cdr * zcm.z, -cdr * zcm.w);
        float4 zbp = *(const float4*)&gZB[jp * BSZ + off];
        *(float4*)&gBb[1][i * BSZ + off] =
            make_float4(-bdr * zbp.x, -bdr * zbp.y, -bdr * zbp.z, -bdr * zbp.w);
    }
    if (tid < 64)
        gy[i * BD + tid] -= scd[tid] * gZy[jm * BD + tid]
                          + sbd[tid] * gZy[jp * BD + tid];
}

// ---------------------------------------------------------------------------
// K2 (levels >= 2): 5 balanced tasks per surviving block (see R13).
// ---------------------------------------------------------------------------
#define K2_SMEM (4 * 64 * 68 * 4)

__global__ void __launch_bounds__(256, 1)
k2_update(int s, int p)
{
    const int i    = 2 * s - 1 + 2 * s * blockIdx.x;
    const int task = blockIdx.y;
    const int jm   = i - s;
    const int jp   = (i + s > 63) ? 63 : (i + s);
    const int tid  = threadIdx.x;

    if (task == 4) {
        __shared__ float sy1[64], sy2[64];
        if (tid < 64) { sy1[tid] = gZy[jm * BD + tid]; sy2[tid] = gZy[jp * BD + tid]; }
        __syncthreads();
        if (tid < 64) {
            float acc = gy[i * BD + tid];
            const float* cp = gCb[p] + i * BSZ + tid * BD;
            const float* bp = gBb[p] + i * BSZ + tid * BD;
#pragma unroll 8
            for (int b = 0; b < 64; b++) acc -= cp[b] * sy1[b] + bp[b] * sy2[b];
            gy[i * BD + tid] = acc;
        }
        return;
    }

    extern __shared__ float sm2[];

    if (task < 2) {
        const int coff = task << 5;
        float* P1 = sm2;
        float* P2 = sm2 + 64 * 68;
        float* Q1 = sm2 + 2 * 64 * 68;
        float* Q2 = sm2 + 2 * 64 * 68 + 64 * 34;

        const float* Cg  = gCb[p] + i * BSZ;
        const float* Bg  = gBb[p] + i * BSZ;
        const float* ZBm = gZB + jm * BSZ;
        const float* ZCp = gZC + jp * BSZ;

        for (int e = tid; e < BSZ; e += 256) {
            int r = e >> 6, c = e & 63;
            P1[r * 68 + c] = Cg[e];
            P2[r * 68 + c] = Bg[e];
        }
        for (int e = tid; e < 2048; e += 256) {
            int k = e >> 5, c = e & 31;
            Q1[k * 34 + c] = ZBm[k * BD + coff + c];
            Q2[k * 34 + c] = ZCp[k * BD + coff + c];
        }
        __syncthreads();

        const int r0 = (tid >> 4) << 2;
        const int c2 = (tid & 15) << 1;
        float acc[4][2];
#pragma unroll
        for (int u = 0; u < 4; u++) { acc[u][0] = 0.f; acc[u][1] = 0.f; }

        for (int k = 0; k < 64; k++) {
            float2 b1 = *(const float2*)&Q1[k * 34 + c2];
            float2 b2 = *(const float2*)&Q2[k * 34 + c2];
#pragma unroll
            for (int u = 0; u < 4; u++) {
                float a1 = P1[(r0 + u) * 68 + k];
                float a2 = P2[(r0 + u) * 68 + k];
                acc[u][0] += a1 * b1.x + a2 * b2.x;
                acc[u][1] += a1 * b1.y + a2 * b2.y;
            }
        }
#pragma unroll
        for (int u = 0; u < 4; u++) {
            float2 o = *(float2*)&gA[i * BSZ + (r0 + u) * BD + coff + c2];
            o.x -= acc[u][0]; o.y -= acc[u][1];
            *(float2*)&gA[i * BSZ + (r0 + u) * BD + coff + c2] = o;
        }
        return;
    }

    float* P1 = sm2;
    float* Q1 = sm2 + 64 * 68;

    const float* p1g = ((task == 2) ? gCb[p] : gBb[p]) + i * BSZ;
    const float* q1g = (task == 2) ? (gZC + jm * BSZ) : (gZB + jp * BSZ);

    for (int e = tid; e < BSZ; e += 256) {
        int r = e >> 6, c = e & 63;
        P1[r * 68 + c] = p1g[e];
        Q1[r * 68 + c] = q1g[e];
    }
    __syncthreads();

    const int r0 = (tid >> 4) << 2;
    const int cc = (tid & 15) << 2;
    float acc[4][4];
#pragma unroll
    for (int u = 0; u < 4; u++)
#pragma unroll
        for (int v = 0; v < 4; v++) acc[u][v] = 0.0f;

    for (int k = 0; k < 64; k++) {
        float4 b1 = *(const float4*)&Q1[k * 68 + cc];
#pragma unroll
        for (int u = 0; u < 4; u++) {
            float a1 = P1[(r0 + u) * 68 + k];
            acc[u][0] += a1 * b1.x;
            acc[u][1] += a1 * b1.y;
            acc[u][2] += a1 * b1.z;
            acc[u][3] += a1 * b1.w;
        }
    }
    float* dst = ((task == 2) ? gCb[p ^ 1] : gBb[p ^ 1]) + i * BSZ;
#pragma unroll
    for (int u = 0; u < 4; u++)
        *(float4*)&dst[(r0 + u) * BD + cc] =
            make_float4(-acc[u][0], -acc[u][1], -acc[u][2], -acc[u][3]);
}

// ---------------------------------------------------------------------------
// Backsub
// ---------------------------------------------------------------------------
__global__ void __launch_bounds__(1024, 1)
backsub_kernel(float* __restrict__ out)
{
    __shared__ float sx[NBLK * BD];
    const int tid = threadIdx.x;
    for (int e = tid; e < NBLK * BD; e += 1024) sx[e] = 0.0f;
    __syncthreads();

    for (int lev = 7; lev >= 1; lev--) {
        int s  = 1 << (lev - 1);
        int ne = (lev == 7) ? 1 : (32 >> (lev - 1));
        for (int idx = tid; idx < ne * 64; idx += 1024) {
            int t = idx >> 6, a = idx & 63;
            int j = s - 1 + 2 * s * t;
            int jm = j - s; if (jm < 0)  jm = 0;
            int jp = j + s; if (jp > 63) jp = 63;
            const float4* zc = (const float4*)(gZC + j * BSZ + a * BD);
            const float4* zb = (const float4*)(gZB + j * BSZ + a * BD);
            float s0 = 0.f, s1 = 0.f, s2 = 0.f, s3 = 0.f;
#pragma unroll
            for (int w = 0; w < 16; w++) {
                float4 c4 = zc[w], b4 = zb[w];
                s0 += c4.x * sx[jm * BD + 4 * w]     + b4.x * sx[jp * BD + 4 * w];
                s1 += c4.y * sx[jm * BD + 4 * w + 1] + b4.y * sx[jp * BD + 4 * w + 1];
                s2 += c4.z * sx[jm * BD + 4 * w + 2] + b4.z * sx[jp * BD + 4 * w + 2];
                s3 += c4.w * sx[jm * BD + 4 * w + 3] + b4.w * sx[jp * BD + 4 * w + 3];
            }
            float acc = gZy[j * BD + a] - (s0 + s1 + s2 + s3);
            sx[j * BD + a]  = acc;
            out[j * BD + a] = acc;
        }
        __syncthreads();
    }
}

// ---------------------------------------------------------------------------
// kernel_launch
// ---------------------------------------------------------------------------
extern "C" void kernel_launch(void* const* d_in, const int* in_sizes, int n_in,
                              void* d_out, int out_size)
{
    const float* h    = (const float*)d_in[0];
    const float* phi  = (const float*)d_in[1];
    const float* base = (const float*)d_in[2];
    const float* over = (const float*)d_in[3];
    const float* melt = (const float*)d_in[4];
    const float* len  = (const float*)d_in[5];
    const int*   adj  = (const int*)  d_in[6];
    const int*   io   = (const int*)  d_in[7];
    float* out = (float*)d_out;

    static int once = []() {
        cudaFuncSetAttribute(k2_update,
                             cudaFuncAttributeMaxDynamicSharedMemorySize,
                             K2_SMEM);
        return 0;
    }();
    (void)once;

    assemble_kernel<<<32, 128>>>(h, phi, base, over, melt, len, adj, io);

    // level 1: eliminate even blocks; diagonal C/B specializations
    k1inv<<<32, 512>>>(1, /*mode=*/0);
    k2_lvl1<<<32, 256>>>();

    // levels 2..6
    for (int lev = 2; lev <= 6; lev++) {
        int s = 1 << (lev - 1);
        int n = 32 >> (lev - 1);
        int p = (lev - 1) & 1;
        k1inv<<<n, 512>>>(s, /*mode=*/1);
        kZ<<<dim3(n, 2), 512>>>(s, p);
        k2_update<<<dim3(n, 5), 256, K2_SMEM>>>(s, p);
    }

    // top block (j = 63): only Zy needed
    k1inv<<<1, 512>>>(64, /*mode=*/2);
    backsub_kernel<<<1, 1024>>>(out);
}

// round 16
// speedup vs baseline: 1.1560x; 1.1560x over previous
#include <cuda_runtime.h>
#include <cuda_bf16.h>

// SubglacialDrainageSystem: L x = f on a 64x64 grid.
// Block cyclic reduction over the 64-block tridiagonal structure (BD=64).
// R16 = R13 config (512-thr rank-4 k1inv, parallel kZ, 5-task k2) with ONE
// critical-path fix: the pipelined next-window 4x4 pivot inverse is hosted on
// lanes 0-15 of warp `it` (the window-column warp, whose update is trivial
// m=u), not warp 0 -- so the serial inverse chain overlaps other warps' work.

#define NBLK 64
#define BD   64
#define BSZ  (BD * BD)

static __device__ float gA [NBLK * BSZ];
static __device__ float gAi[NBLK * BSZ];
static __device__ float gCb[2][NBLK * BSZ];
static __device__ float gBb[2][NBLK * BSZ];
static __device__ float gy [NBLK * BD];
static __device__ float gZC[NBLK * BSZ];
static __device__ float gZB[NBLK * BSZ];
static __device__ float gZy[NBLK * BD];

// ---------------------------------------------------------------------------
// Assembly
// ---------------------------------------------------------------------------
__global__ void assemble_kernel(const float* __restrict__ h,
                                const float* __restrict__ phi,
                                const float* __restrict__ base,
                                const float* __restrict__ over,
                                const float* __restrict__ melt,
                                const float* __restrict__ len,
                                const int*   __restrict__ adj,
                                const int*   __restrict__ io)
{
    int i = blockIdx.x * blockDim.x + threadIdx.x;
    if (i >= NBLK * BD) return;
    int r = i >> 6, a = i & 63;

    float4 z = make_float4(0.f, 0.f, 0.f, 0.f);
    float4* rowA = (float4*)(gA     + r * BSZ + a * BD);
    float4* rowC = (float4*)(gCb[0] + r * BSZ + a * BD);
    float4* rowB = (float4*)(gBb[0] + r * BSZ + a * BD);
#pragma unroll
    for (int b = 0; b < 16; b++) { rowA[b] = z; rowC[b] = z; rowB[b] = z; }

    const bool infl = (io[i] == 1);
    const double hi = (double)h[i];
    const double pi = (double)phi[i];
    double diag = 0.0, cf0 = 0.0, cf1 = 0.0, cf2 = 0.0, cf3 = 0.0;

#pragma unroll
    for (int k = 0; k < 4; k++) {           // 0 north, 1 south, 2 west, 3 east
        int   j = adj[i * 4 + k];
        float L = len[i * 4 + k];
        double cc = 0.0;
        if (j >= 0 && L > 0.0f && !infl) {
            double hf   = 0.5 * (hi + (double)h[j]);
            double dphi = fabs(pi - (double)phi[j]);
            double g    = fmax(dphi, 1e-12) / (double)L;
            cc = -0.01 * pow(hf, 1.25) * (double)L * rsqrt(g);
            diag -= cc;
        }
        if (k == 0) cf0 = cc; else if (k == 1) cf1 = cc;
        else if (k == 2) cf2 = cc; else cf3 = cc;
    }

    gA[r * BSZ + a * BD + a] = infl ? 1.0f : (float)diag;
    if (a > 0)  gA[r * BSZ + a * BD + (a - 1)] = (float)cf2;
    if (a < 63) gA[r * BSZ + a * BD + (a + 1)] = (float)cf3;
    gCb[0][r * BSZ + a * BD + a] = (float)cf0;
    gBb[0][r * BSZ + a * BD + a] = (float)cf1;
    gy[i] = infl ? (float)((double)base[i] - (double)over[i]) : melt[i];
}

// ---------------------------------------------------------------------------
// 16-lane 4x4 Gauss-Jordan inverse (lanes 0-15 of the calling warp).
// ---------------------------------------------------------------------------
__device__ __forceinline__ float gj4_inverse_lane(float av, int r, int c)
{
    const unsigned am = 0xFFFFu;
    float iv = (r == c) ? 1.0f : 0.0f;
#pragma unroll
    for (int p = 0; p < 4; p++) {
        float app = __shfl_sync(am, av, p * 4 + p);
        float apc = __shfl_sync(am, av, p * 4 + c);
        float ipc = __shfl_sync(am, iv, p * 4 + c);
        float arp = __shfl_sync(am, av, r * 4 + p);
        float rinv = __fdividef(1.0f, app);
        if (r == p) { av = apc * rinv;          iv = ipc * rinv; }
        else        { float f = arp * rinv; av -= f * apc; iv -= f * ipc; }
    }
    return iv;
}

// ---------------------------------------------------------------------------
// K1: pipelined rank-4 in-place GJ inversion of [A | y] (width 65).
// 512 threads: rg = tid&31 owns rows {2rg, 2rg+1}; cg = tid>>5 owns cols
// [4cg, 4cg+4) (+y if cg==15). One __syncthreads per iteration; next-window
// 4x4 pivot inverse pipelined on lanes 0-15 of warp `it` (window warp).
// mode 0: epilogue ZC/ZB by diagonal column scaling (level 1)
// mode 1: epilogue writes Ainv to gAi (kZ forms ZC/ZB)
// mode 2: epilogue Zy only (top block)
// ---------------------------------------------------------------------------
__global__ void __launch_bounds__(512, 1)
k1inv(int s, int mode)
{
    const int j   = s - 1 + 2 * s * blockIdx.x;
    const int tid = threadIdx.x;
    const int rg  = tid & 31;
    const int cg  = tid >> 5;
    const int c0  = 4 * cg;
    const int r0  = 2 * rg;

    const float* Aj = gA + j * BSZ;

    float m[2][4], my[2];
#pragma unroll
    for (int r = 0; r < 2; r++) {
        float4 v = *(const float4*)&Aj[(r0 + r) * BD + c0];
        m[r][0] = v.x; m[r][1] = v.y; m[r][2] = v.z; m[r][3] = v.w;
        my[r] = (cg == 15) ? gy[j * BD + r0 + r] : 0.0f;
    }

    __shared__ float s_prow[2][4][68];     // current pivot rows (full width)
    __shared__ float s_pcol[2][64][4];     // current pivot cols, row-major f4
    __shared__ float s_pblk[2][4][4];      // NEXT window 4x4 block (raw)
    __shared__ float s_W[2][16];           // P^{-1}, row-major [4r+t]

    // ---- prologue: window 0 --------------------------------------------
    if (rg < 2) {                          // rows 0..3
#pragma unroll
        for (int r = 0; r < 2; r++) {
            *(float4*)&s_prow[0][r0 + r][c0] =
                make_float4(m[r][0], m[r][1], m[r][2], m[r][3]);
            if (cg == 15) s_prow[0][r0 + r][64] = my[r];
        }
    }
    if (cg == 0) {
#pragma unroll
        for (int r = 0; r < 2; r++)
            *(float4*)&s_pcol[0][r0 + r][0] =
                make_float4(m[r][0], m[r][1], m[r][2], m[r][3]);
    }
    if (cg == 1 && (rg >> 1) == 1) {       // rows 4..7, cols 4..7
#pragma unroll
        for (int r = 0; r < 2; r++)
#pragma unroll
            for (int t = 0; t < 4; t++) s_pblk[0][r0 + r - 4][t] = m[r][t];
    }
    __syncthreads();
    if (tid < 16)
        s_W[0][tid] = gj4_inverse_lane(s_pcol[0][tid >> 2][tid & 3],
                                       tid >> 2, tid & 3);
    __syncthreads();

    // ---- 16 pipelined rank-4 sweep iterations ---------------------------
    for (int it = 0; it < 16; it++) {
        const int b  = it & 1;
        const int nb = b ^ 1;
        const int kn = 4 * it + 4;
        const bool ispiv = ((rg >> 1) == it);

        float4 W0 = *(const float4*)&s_W[b][0];
        float4 W1 = *(const float4*)&s_W[b][4];
        float4 W2 = *(const float4*)&s_W[b][8];
        float4 W3 = *(const float4*)&s_W[b][12];

        float u[2][4];
        if (ispiv) {
            bool hi = (rg & 1);
            float4 wa = hi ? W2 : W0;      // local pivot row 2*hi
            float4 wb = hi ? W3 : W1;      // local pivot row 2*hi+1
            u[0][0] = wa.x; u[0][1] = wa.y; u[0][2] = wa.z; u[0][3] = wa.w;
            u[1][0] = wb.x; u[1][1] = wb.y; u[1][2] = wb.z; u[1][3] = wb.w;
        } else {
#pragma unroll
            for (int r = 0; r < 2; r++) {
                float4 v = *(const float4*)&s_pcol[b][r0 + r][0];
                u[r][0] = -(v.x * W0.x + v.y * W1.x + v.z * W2.x + v.w * W3.x);
                u[r][1] = -(v.x * W0.y + v.y * W1.y + v.z * W2.y + v.w * W3.y);
                u[r][2] = -(v.x * W0.z + v.y * W1.z + v.z * W2.z + v.w * W3.z);
                u[r][3] = -(v.x * W0.w + v.y * W1.w + v.z * W2.w + v.w * W3.w);
            }
        }

        if (cg == it) {
            // window columns: Q <- -Q P^{-1} = u (non-pivot); P <- W (pivot)
#pragma unroll
            for (int r = 0; r < 2; r++)
#pragma unroll
                for (int t = 0; t < 4; t++) m[r][t] = u[r][t];
        } else {
            float4 p0 = *(const float4*)&s_prow[b][0][c0];
            float4 p1 = *(const float4*)&s_prow[b][1][c0];
            float4 p2 = *(const float4*)&s_prow[b][2][c0];
            float4 p3 = *(const float4*)&s_prow[b][3][c0];
#pragma unroll
            for (int r = 0; r < 2; r++) {
                float b0 = ispiv ? 0.0f : m[r][0];
                float b1 = ispiv ? 0.0f : m[r][1];
                float b2 = ispiv ? 0.0f : m[r][2];
                float b3 = ispiv ? 0.0f : m[r][3];
                m[r][0] = b0 + u[r][0] * p0.x + u[r][1] * p1.x + u[r][2] * p2.x + u[r][3] * p3.x;
                m[r][1] = b1 + u[r][0] * p0.y + u[r][1] * p1.y + u[r][2] * p2.y + u[r][3] * p3.y;
                m[r][2] = b2 + u[r][0] * p0.z + u[r][1] * p1.z + u[r][2] * p2.z + u[r][3] * p3.z;
                m[r][3] = b3 + u[r][0] * p0.w + u[r][1] * p1.w + u[r][2] * p2.w + u[r][3] * p3.w;
            }
        }
        if (cg == 15) {                    // y column: unconditional
            float py0 = s_prow[b][0][64], py1 = s_prow[b][1][64];
            float py2 = s_prow[b][2][64], py3 = s_prow[b][3][64];
#pragma unroll
            for (int r = 0; r < 2; r++) {
                float bb = ispiv ? 0.0f : my[r];
                my[r] = bb + u[r][0] * py0 + u[r][1] * py1 + u[r][2] * py2 + u[r][3] * py3;
            }
        }

        if (it < 15) {
            // pipelined next-window pivot inverse: lanes 0-15 of warp `it`
            // (the window-column warp: its m-update above was trivial m=u).
            if (cg == it && rg < 16) {
                int r4 = rg >> 2, ccl = rg & 3;
                float4 v = *(const float4*)&s_pcol[b][kn + r4][0];
                float t0 = -(v.x * W0.x + v.y * W1.x + v.z * W2.x + v.w * W3.x);
                float t1 = -(v.x * W0.y + v.y * W1.y + v.z * W2.y + v.w * W3.y);
                float t2 = -(v.x * W0.z + v.y * W1.z + v.z * W2.z + v.w * W3.z);
                float t3 = -(v.x * W0.w + v.y * W1.w + v.z * W2.w + v.w * W3.w);
                float av = s_pblk[b][r4][ccl]
                         + t0 * s_prow[b][0][kn + ccl]
                         + t1 * s_prow[b][1][kn + ccl]
                         + t2 * s_prow[b][2][kn + ccl]
                         + t3 * s_prow[b][3][kn + ccl];
                s_W[nb][rg] = gj4_inverse_lane(av, r4, ccl);
            }
            if ((rg >> 1) == it + 1) {     // next pivot rows
#pragma unroll
                for (int r = 0; r < 2; r++) {
                    *(float4*)&s_prow[nb][r0 + r - kn][c0] =
                        make_float4(m[r][0], m[r][1], m[r][2], m[r][3]);
                    if (cg == 15) s_prow[nb][r0 + r - kn][64] = my[r];
                }
            }
            if (cg == it + 1) {            // next pivot cols
#pragma unroll
                for (int r = 0; r < 2; r++)
                    *(float4*)&s_pcol[nb][r0 + r][0] =
                        make_float4(m[r][0], m[r][1], m[r][2], m[r][3]);
            }
            if (it <= 13 && cg == it + 2 && (rg >> 1) == it + 2) {
#pragma unroll
                for (int r = 0; r < 2; r++)
#pragma unroll
                    for (int t = 0; t < 4; t++)
                        s_pblk[nb][r0 + r - (kn + 4)][t] = m[r][t];
            }
        }
        __syncthreads();
    }

    // ---- epilogue --------------------------------------------------------
    if (cg == 15) {
        gZy[j * BD + r0]     = my[0];
        gZy[j * BD + r0 + 1] = my[1];
    }

    if (mode == 0) {
        // level 1: C, B diagonal -> ZC = Ainv * diag(c), ZB = Ainv * diag(b)
        const float* Cj = gCb[0] + j * BSZ;
        const float* Bj = gBb[0] + j * BSZ;
        float cd[4], bd[4];
#pragma unroll
        for (int t = 0; t < 4; t++) {
            cd[t] = Cj[(c0 + t) * 65];     // diagonal entry, col c0+t
            bd[t] = Bj[(c0 + t) * 65];
        }
#pragma unroll
        for (int r = 0; r < 2; r++) {
            *(float4*)&gZC[j * BSZ + (r0 + r) * BD + c0] =
                make_float4(m[r][0] * cd[0], m[r][1] * cd[1],
                            m[r][2] * cd[2], m[r][3] * cd[3]);
            *(float4*)&gZB[j * BSZ + (r0 + r) * BD + c0] =
                make_float4(m[r][0] * bd[0], m[r][1] * bd[1],
                            m[r][2] * bd[2], m[r][3] * bd[3]);
        }
    } else if (mode == 1) {
        // levels 2-6: store Ainv; kZ forms ZC/ZB in parallel CTAs
#pragma unroll
        for (int r = 0; r < 2; r++)
            *(float4*)&gAi[j * BSZ + (r0 + r) * BD + c0] =
                make_float4(m[r][0], m[r][1], m[r][2], m[r][3]);
    }
    // mode 2: Zy only
}

// ---------------------------------------------------------------------------
// kZ: ZC = Ainv * C (by=0) or ZB = Ainv * B (by=1). One 64^3 GEMM per CTA,
// Ainv staged in smem (pad 65), C/B streamed via __ldg (warp-broadcast).
// ---------------------------------------------------------------------------
__global__ void __launch_bounds__(512, 1)
kZ(int s, int p)
{
    const int j     = s - 1 + 2 * s * blockIdx.x;
    const int which = blockIdx.y;
    const int tid   = threadIdx.x;
    const int rg    = tid & 31;
    const int cg    = tid >> 5;
    const int c0    = 4 * cg;
    const int r0    = 2 * rg;

    const float* src = (which ? gBb[p] : gCb[p]) + j * BSZ;
    float*       dst = (which ? gZB    : gZC)    + j * BSZ;

    __shared__ float sAi[64 * 65];
    for (int e = tid; e < BSZ; e += 512) {
        int r = e >> 6, c = e & 63;
        sAi[r * 65 + c] = gAi[j * BSZ + e];
    }
    __syncthreads();

    float4 acc0 = make_float4(0.f, 0.f, 0.f, 0.f);
    float4 acc1 = acc0;
#pragma unroll 4
    for (int k = 0; k < 64; k++) {
        float a0 = sAi[r0 * 65 + k];
        float a1 = sAi[(r0 + 1) * 65 + k];
        float4 v = __ldg((const float4*)&src[k * BD + c0]);
        acc0.x += a0 * v.x; acc0.y += a0 * v.y;
        acc0.z += a0 * v.z; acc0.w += a0 * v.w;
        acc1.x += a1 * v.x; acc1.y += a1 * v.y;
        acc1.z += a1 * v.z; acc1.w += a1 * v.w;
    }
    *(float4*)&dst[r0 * BD + c0]       = acc0;
    *(float4*)&dst[(r0 + 1) * BD + c0] = acc1;
}

// ---------------------------------------------------------------------------
// K2 level 1: C_i, B_i diagonal -> all Schur updates are row scalings.
// ---------------------------------------------------------------------------
__global__ void __launch_bounds__(256, 1)
k2_lvl1()
{
    const int i   = 1 + 2 * blockIdx.x;
    const int jm  = i - 1;
    const int jp  = (i + 1 > 63) ? 63 : (i + 1);
    const int tid = threadIdx.x;

    __shared__ float scd[64], sbd[64];
    if (tid < 64) {
        scd[tid] = gCb[0][i * BSZ + tid * 65];
        sbd[tid] = gBb[0][i * BSZ + tid * 65];
    }
    __syncthreads();

    for (int e = tid; e < 1024; e += 256) {
        int r  = e >> 4;
        int c4 = (e & 15) << 2;
        float cdr = scd[r], bdr = sbd[r];
        int off = r * BD + c4;

        float4 zbm = *(const float4*)&gZB[jm * BSZ + off];
        float4 zcp = *(const float4*)&gZC[jp * BSZ + off];
        float4 a   = *(const float4*)&gA [i * BSZ + off];
        a.x -= cdr * zbm.x + bdr * zcp.x;
        a.y -= cdr * zbm.y + bdr * zcp.y;
        a.z -= cdr * zbm.z + bdr * zcp.z;
        a.w -= cdr * zbm.w + bdr * zcp.w;
        *(float4*)&gA[i * BSZ + off] = a;

        float4 zcm = *(const float4*)&gZC[jm * BSZ + off];
        *(float4*)&gCb[1][i * BSZ + off] =
            make_float4(-cdr * zcm.x, -cdr * zcm.y, -cdr * zcm.z, -cdr * zcm.w);
        float4 zbp = *(const float4*)&gZB[jp * BSZ + off];
        *(float4*)&gBb[1][i * BSZ + off] =
            make_float4(-bdr * zbp.x, -bdr * zbp.y, -bdr * zbp.z, -bdr * zbp.w);
    }
    if (tid < 64)
        gy[i * BD + tid] -= scd[tid] * gZy[jm * BD + tid]
                          + sbd[tid] * gZy[jp * BD + tid];
}

// ---------------------------------------------------------------------------
// K2 (levels >= 2): 5 balanced tasks per surviving block i:
//   task 0/1: A[:, half] -= C*ZB_jm[:,half] + B*ZC_jp[:,half]
//   task 2:   C' = -C*ZC_jm        task 3: B' = -B*ZB_jp
//   task 4:   y -= C*Zy_jm + B*Zy_jp
// ---------------------------------------------------------------------------
#define K2_SMEM (4 * 64 * 68 * 4)

__global__ void __launch_bounds__(256, 1)
k2_update(int s, int p)
{
    const int i    = 2 * s - 1 + 2 * s * blockIdx.x;
    const int task = blockIdx.y;
    const int jm   = i - s;
    const int jp   = (i + s > 63) ? 63 : (i + s);
    const int tid  = threadIdx.x;

    if (task == 4) {
        __shared__ float sy1[64], sy2[64];
        if (tid < 64) { sy1[tid] = gZy[jm * BD + tid]; sy2[tid] = gZy[jp * BD + tid]; }
        __syncthreads();
        if (tid < 64) {
            float acc = gy[i * BD + tid];
            const float* cp = gCb[p] + i * BSZ + tid * BD;
            const float* bp = gBb[p] + i * BSZ + tid * BD;
#pragma unroll 8
            for (int b = 0; b < 64; b++) acc -= cp[b] * sy1[b] + bp[b] * sy2[b];
            gy[i * BD + tid] = acc;
        }
        return;
    }

    extern __shared__ float sm2[];

    if (task < 2) {
        const int coff = task << 5;
        float* P1 = sm2;                  // C_i  [64][68]
        float* P2 = sm2 + 64 * 68;        // B_i  [64][68]
        float* Q1 = sm2 + 2 * 64 * 68;            // ZB_jm panel [64][34]
        float* Q2 = sm2 + 2 * 64 * 68 + 64 * 34;  // ZC_jp panel [64][34]

        const float* Cg  = gCb[p] + i * BSZ;
        const float* Bg  = gBb[p] + i * BSZ;
        const float* ZBm = gZB + jm * BSZ;
        const float* ZCp = gZC + jp * BSZ;

        for (int e = tid; e < BSZ; e += 256) {
            int r = e >> 6, c = e & 63;
            P1[r * 68 + c] = Cg[e];
            P2[r * 68 + c] = Bg[e];
        }
        for (int e = tid; e < 2048; e += 256) {
            int k = e >> 5, c = e & 31;
            Q1[k * 34 + c] = ZBm[k * BD + coff + c];
            Q2[k * 34 + c] = ZCp[k * BD + coff + c];
        }
        __syncthreads();

        const int r0 = (tid >> 4) << 2;
        const int c2 = (tid & 15) << 1;
        float acc[4][2];
#pragma unroll
        for (int u = 0; u < 4; u++) { acc[u][0] = 0.f; acc[u][1] = 0.f; }

        for (int k = 0; k < 64; k++) {
            float2 b1 = *(const float2*)&Q1[k * 34 + c2];
            float2 b2 = *(const float2*)&Q2[k * 34 + c2];
#pragma unroll
            for (int u = 0; u < 4; u++) {
                float a1 = P1[(r0 + u) * 68 + k];
                float a2 = P2[(r0 + u) * 68 + k];
                acc[u][0] += a1 * b1.x + a2 * b2.x;
                acc[u][1] += a1 * b1.y + a2 * b2.y;
            }
        }
#pragma unroll
        for (int u = 0; u < 4; u++) {
            float2 o = *(float2*)&gA[i * BSZ + (r0 + u) * BD + coff + c2];
            o.x -= acc[u][0]; o.y -= acc[u][1];
            *(float2*)&gA[i * BSZ + (r0 + u) * BD + coff + c2] = o;
        }
        return;
    }

    float* P1 = sm2;
    float* Q1 = sm2 + 64 * 68;

    const float* p1g = ((task == 2) ? gCb[p] : gBb[p]) + i * BSZ;
    const float* q1g = (task == 2) ? (gZC + jm * BSZ) : (gZB + jp * BSZ);

    for (int e = tid; e < BSZ; e += 256) {
        int r = e >> 6, c = e & 63;
        P1[r * 68 + c] = p1g[e];
        Q1[r * 68 + c] = q1g[e];
    }
    __syncthreads();

    const int r0 = (tid >> 4) << 2;
    const int cc = (tid & 15) << 2;
    float acc[4][4];
#pragma unroll
    for (int u = 0; u < 4; u++)
#pragma unroll
        for (int v = 0; v < 4; v++) acc[u][v] = 0.0f;

    for (int k = 0; k < 64; k++) {
        float4 b1 = *(const float4*)&Q1[k * 68 + cc];
#pragma unroll
        for (int u = 0; u < 4; u++) {
            float a1 = P1[(r0 + u) * 68 + k];
            acc[u][0] += a1 * b1.x;
            acc[u][1] += a1 * b1.y;
            acc[u][2] += a1 * b1.z;
            acc[u][3] += a1 * b1.w;
        }
    }
    float* dst = ((task == 2) ? gCb[p ^ 1] : gBb[p ^ 1]) + i * BSZ;
#pragma unroll
    for (int u = 0; u < 4; u++)
        *(float4*)&dst[(r0 + u) * BD + cc] =
            make_float4(-acc[u][0], -acc[u][1], -acc[u][2], -acc[u][3]);
}

// ---------------------------------------------------------------------------
// Backsub
// ---------------------------------------------------------------------------
__global__ void __launch_bounds__(1024, 1)
backsub_kernel(float* __restrict__ out)
{
    __shared__ float sx[NBLK * BD];
    const int tid = threadIdx.x;
    for (int e = tid; e < NBLK * BD; e += 1024) sx[e] = 0.0f;
    __syncthreads();

    for (int lev = 7; lev >= 1; lev--) {
        int s  = 1 << (lev - 1);
        int ne = (lev == 7) ? 1 : (32 >> (lev - 1));
        for (int idx = tid; idx < ne * 64; idx += 1024) {
            int t = idx >> 6, a = idx & 63;
            int j = s - 1 + 2 * s * t;
            int jm = j - s; if (jm < 0)  jm = 0;
            int jp = j + s; if (jp > 63) jp = 63;
            const float4* zc = (const float4*)(gZC + j * BSZ + a * BD);
            const float4* zb = (const float4*)(gZB + j * BSZ + a * BD);
            float s0 = 0.f, s1 = 0.f, s2 = 0.f, s3 = 0.f;
#pragma unroll
            for (int w = 0; w < 16; w++) {
                float4 c4 = zc[w], b4 = zb[w];
                s0 += c4.x * sx[jm * BD + 4 * w]     + b4.x * sx[jp * BD + 4 * w];
                s1 += c4.y * sx[jm * BD + 4 * w + 1] + b4.y * sx[jp * BD + 4 * w + 1];
                s2 += c4.z * sx[jm * BD + 4 * w + 2] + b4.z * sx[jp * BD + 4 * w + 2];
                s3 += c4.w * sx[jm * BD + 4 * w + 3] + b4.w * sx[jp * BD + 4 * w + 3];
            }
            float acc = gZy[j * BD + a] - (s0 + s1 + s2 + s3);
            sx[j * BD + a]  = acc;
            out[j * BD + a] = acc;
        }
        __syncthreads();
    }
}

// ---------------------------------------------------------------------------
// kernel_launch
// ---------------------------------------------------------------------------
extern "C" void kernel_launch(void* const* d_in, const int* in_sizes, int n_in,
                              void* d_out, int out_size)
{
    const float* h    = (const float*)d_in[0];
    const float* phi  = (const float*)d_in[1];
    const float* base = (const float*)d_in[2];
    const float* over = (const float*)d_in[3];
    const float* melt = (const float*)d_in[4];
    const float* len  = (const float*)d_in[5];
    const int*   adj  = (const int*)  d_in[6];
    const int*   io   = (const int*)  d_in[7];
    float* out = (float*)d_out;

    static int once = []() {
        cudaFuncSetAttribute(k2_update,
                             cudaFuncAttributeMaxDynamicSharedMemorySize,
                             K2_SMEM);
        return 0;
    }();
    (void)once;

    assemble_kernel<<<32, 128>>>(h, phi, base, over, melt, len, adj, io);

    // level 1: eliminate even blocks; diagonal C/B specializations
    k1inv<<<32, 512>>>(1, /*mode=*/0);
    k2_lvl1<<<32, 256>>>();

    // levels 2..6
    for (int lev = 2; lev <= 6; lev++) {
        int s = 1 << (lev - 1);
        int n = 32 >> (lev - 1);
        int p = (lev - 1) & 1;
        k1inv<<<n, 512>>>(s, /*mode=*/1);
        kZ<<<dim3(n, 2), 512>>>(s, p);
        k2_update<<<dim3(n, 5), 256, K2_SMEM>>>(s, p);
    }

    // top block (j = 63): only Zy needed
    k1inv<<<1, 512>>>(64, /*mode=*/2);
    backsub_kernel<<<1, 1024>>>(out);
}